// round 2
// baseline (speedup 1.0000x reference)
#include <cuda_runtime.h>
#include <math.h>

// ConvLSTM, 16 sequential fused conv+LSTM steps — FFMA2 (fma.rn.f32x2) version.
// x: (8,16,64,64,64) f32, Wk: (256,128,3,3) f32
// out: [hid (8*64*64*64) | cell (8*64*64*64)] f32
//
// Block: 16x16 spatial tile x 64 out-channels = {i,f,o,g} x 16 hidden ch.
// Thread: 4 x-positions x 16 channels = 64 fp32 acc held as 32 f32x2 pairs
// (pairs along the channel dim so the weight pair is one contiguous LDS.64
// and the spatial operand is a duplicated scalar).

#define TILE 16
#define ICC  8

__device__ float g_hbuf[2][8u * 64u * 64u * 64u];

__device__ __forceinline__ unsigned long long ffma2(unsigned long long a,
                                                    unsigned long long b,
                                                    unsigned long long c)
{
    unsigned long long d;
    asm("fma.rn.f32x2 %0, %1, %2, %3;" : "=l"(d) : "l"(a), "l"(b), "l"(c));
    return d;
}

__device__ __forceinline__ unsigned long long dup2(float v)
{
    unsigned long long d;
    asm("mov.b64 %0, {%1, %1};" : "=l"(d) : "f"(v));
    return d;
}

__device__ __forceinline__ float lo32(unsigned long long v)
{
    return __int_as_float((int)(unsigned)(v & 0xffffffffull));
}
__device__ __forceinline__ float hi32(unsigned long long v)
{
    return __int_as_float((int)(unsigned)(v >> 32));
}

__global__ __launch_bounds__(256, 2)
void convlstm_step(const float* __restrict__ x,
                   const float* __restrict__ Wk,
                   float* __restrict__ hid_out,
                   float* __restrict__ cell_io,
                   int t, int last)
{
    __shared__ __align__(16) float in_s[ICC][18][20]; // tile + halo, 16B-aligned rows
    __shared__ __align__(16) float w_s[72][66];       // [r][oc_local], pad 66 (8B pairs ok)

    const int tid = threadIdx.x;
    const int og  = tid >> 6;        // 0..3 : 4-hidden-ch subgroup
    const int sg  = tid & 63;
    const int row = sg >> 2;         // 0..15
    const int col = (sg & 3) << 2;   // 0,4,8,12

    const int ty  = blockIdx.x >> 2;
    const int tx  = blockIdx.x & 3;
    const int ocg = blockIdx.y;      // hidden-channel group (16 each)
    const int b   = blockIdx.z;

    const float* h_in = g_hbuf[t & 1];
    float* h_out = last ? hid_out : g_hbuf[(t + 1) & 1];

    // acc2[p][g*2+pp] = channels (g*4 + pp*2, g*4 + pp*2 + 1) for spatial p
    unsigned long long acc2[4][8];
#pragma unroll
    for (int p = 0; p < 4; p++)
#pragma unroll
        for (int q = 0; q < 8; q++) acc2[p][q] = 0ull;

    const int nic = (t == 0) ? 64 : 128;   // t=0: h==0, skip h half

    for (int ic0 = 0; ic0 < nic; ic0 += ICC) {
        __syncthreads();
        const float* src = (ic0 < 64)
            ? x + (((size_t)b * 16 + t) * 64 + ic0) * 4096
            : h_in + ((size_t)b * 64 + (ic0 - 64)) * 4096;

        // stage input tile (with halo, zero-padded at image edges)
        for (int i = tid; i < ICC * 18 * 18; i += 256) {
            int ic  = i / 324;
            int rem = i - ic * 324;
            int yy  = rem / 18;
            int xx  = rem - yy * 18;
            int gy  = ty * TILE - 1 + yy;
            int gx  = tx * TILE - 1 + xx;
            float v = 0.f;
            if ((unsigned)gy < 64u && (unsigned)gx < 64u)
                v = src[ic * 4096 + gy * 64 + gx];
            in_s[ic][yy][xx] = v;
        }
        // stage weights: coalesced global (72 contiguous per oc),
        // transpose into [r][oc_local] so channel pairs are contiguous
        for (int i = tid; i < 64 * 72; i += 256) {
            int ocl = i / 72;
            int r   = i - ocl * 72;
            int oc  = (ocl >> 4) * 64 + ocg * 16 + (ocl & 15);  // gate*64 + hc
            w_s[r][ocl] = Wk[(size_t)oc * 1152 + (size_t)ic0 * 9 + r];
        }
        __syncthreads();

#pragma unroll
        for (int ic = 0; ic < ICC; ic++) {
#pragma unroll
            for (int ky = 0; ky < 3; ky++) {
                const float* rowp = &in_s[ic][row + ky][0];
                float4 xa = *(const float4*)(rowp + col);
                float4 xb = *(const float4*)(rowp + col + 4);
                unsigned long long xd[6];
                xd[0] = dup2(xa.x); xd[1] = dup2(xa.y);
                xd[2] = dup2(xa.z); xd[3] = dup2(xa.w);
                xd[4] = dup2(xb.x); xd[5] = dup2(xb.y);
#pragma unroll
                for (int kx = 0; kx < 3; kx++) {
                    const int r = ic * 9 + ky * 3 + kx;
                    const float* wr = &w_s[r][og * 4];
#pragma unroll
                    for (int g = 0; g < 4; g++) {
                        unsigned long long w01 =
                            *(const unsigned long long*)(wr + g * 16);
                        unsigned long long w23 =
                            *(const unsigned long long*)(wr + g * 16 + 2);
#pragma unroll
                        for (int p = 0; p < 4; p++) {
                            acc2[p][g * 2 + 0] =
                                ffma2(xd[kx + p], w01, acc2[p][g * 2 + 0]);
                            acc2[p][g * 2 + 1] =
                                ffma2(xd[kx + p], w23, acc2[p][g * 2 + 1]);
                        }
                    }
                }
            }
        }
    }

    // fused LSTM pointwise epilogue
    const int gy  = ty * TILE + row;
    const int gx0 = tx * TILE + col;
#pragma unroll
    for (int jj = 0; jj < 4; jj++) {
        const int pp  = jj >> 1;     // pair index within gate group
        const int ln  = jj & 1;      // lane within pair
        const int hc  = ocg * 16 + og * 4 + jj;
        const size_t base = (((size_t)b * 64 + hc) * 64 + gy) * 64 + gx0;
#pragma unroll
        for (int p = 0; p < 4; p++) {
            unsigned long long vi = acc2[p][0 * 2 + pp];
            unsigned long long vf = acc2[p][1 * 2 + pp];
            unsigned long long vo = acc2[p][2 * 2 + pp];
            unsigned long long vg = acc2[p][3 * 2 + pp];
            float ai = ln ? hi32(vi) : lo32(vi);
            float af = ln ? hi32(vf) : lo32(vf);
            float ao = ln ? hi32(vo) : lo32(vo);
            float ag = ln ? hi32(vg) : lo32(vg);
            float iv = 1.f / (1.f + __expf(-ai));
            float fv = 1.f / (1.f + __expf(-af));
            float ov = 1.f / (1.f + __expf(-ao));
            float gv = tanhf(ag);
            float cold = (t == 0) ? 0.f : cell_io[base + p];
            float cnew = fv * cold + iv * gv;
            cell_io[base + p] = cnew;
            h_out[base + p]   = ov * tanhf(cnew);
        }
    }
}

extern "C" void kernel_launch(void* const* d_in, const int* in_sizes, int n_in,
                              void* d_out, int out_size)
{
    const float* x  = (const float*)d_in[0];
    const float* Wk = (const float*)d_in[1];
    float* out  = (float*)d_out;
    float* hid  = out;                  // first half
    float* cell = out + out_size / 2;   // second half

    dim3 grid(16, 4, 8), blk(256);
    for (int t = 0; t < 16; t++)
        convlstm_step<<<grid, blk>>>(x, Wk, hid, cell, t, t == 15 ? 1 : 0);
}

// round 4
// speedup vs baseline: 3.3681x; 3.3681x over previous
#include <cuda_runtime.h>
#include <cuda_bf16.h>
#include <math.h>

// ConvLSTM via tensor cores (mma.sync m16n8k16 bf16, 3-term hi/lo split).
// x: (8,16,64,64,64) f32, Wk: (256,128,3,3) f32
// out: [hid | cell], each 8*64*64*64 f32 (NCHW).
//
// Implicit GEMM per step: A = pixels x ic (channel-last bf16 hi/lo),
// B = W[oc][ic] bf16 hi/lo; D += Ah*Bh + Ah*Bl + Al*Bh (fp32 acc).
// Block: 128 pixels (2 rows x 64) x 64 oc = {i,f,o,g} x 16 hidden ch.
// h recurrence PARITY DOUBLE-BUFFERED (read g_hs[t&1], write g_hs[(t+1)&1])
// to avoid the cross-block read/write race within a step.

#define HW 64

__device__ __nv_bfloat16 g_xs[2][8][16][HW][HW][64];   // x, channel-last hi/lo
__device__ __nv_bfloat16 g_hs[2][2][8][HW][HW][64];    // [parity][split] h hi/lo
__device__ __nv_bfloat16 g_wb[2][9][256][128];         // weights [sp][tap][oc][ic]

// ---------------- prep kernels ----------------

__global__ void prep_w(const float* __restrict__ Wk)
{
    int i = blockIdx.x * blockDim.x + threadIdx.x;   // over 256*128*9
    if (i >= 256 * 128 * 9) return;
    int tap = i % 9;
    int ic  = (i / 9) % 128;
    int oc  = i / (9 * 128);
    float v = Wk[(size_t)(oc * 128 + ic) * 9 + tap];
    __nv_bfloat16 hi = __float2bfloat16(v);
    float lo = v - __bfloat162float(hi);
    g_wb[0][tap][oc][ic] = hi;
    g_wb[1][tap][oc][ic] = __float2bfloat16(lo);
}

__global__ void prep_x(const float* __restrict__ x)
{
    __shared__ float tile[64][65];
    int y  = blockIdx.x & 63;
    int bt = blockIdx.x >> 6;               // b*16 + t
    const float* src = x + (size_t)bt * 64 * 4096 + y * 64;
    for (int i = threadIdx.x; i < 64 * 64; i += 256) {
        int ic = i >> 6, xx = i & 63;
        tile[ic][xx] = src[ic * 4096 + xx];
    }
    __syncthreads();
    int b = bt >> 4, t = bt & 15;
    for (int i = threadIdx.x; i < 64 * 64; i += 256) {
        int xx = i >> 6, ic = i & 63;
        float v = tile[ic][xx];
        __nv_bfloat16 hi = __float2bfloat16(v);
        g_xs[0][b][t][y][xx][ic] = hi;
        g_xs[1][b][t][y][xx][ic] = __float2bfloat16(v - __bfloat162float(hi));
    }
}

// ---------------- mma helpers ----------------

__device__ __forceinline__ void ldsm4(unsigned &r0, unsigned &r1,
                                      unsigned &r2, unsigned &r3, unsigned a)
{
    asm volatile("ldmatrix.sync.aligned.m8n8.x4.shared.b16 {%0,%1,%2,%3}, [%4];"
                 : "=r"(r0), "=r"(r1), "=r"(r2), "=r"(r3) : "r"(a));
}

__device__ __forceinline__ void mma_bf16(float* c, const unsigned* a, const unsigned* b)
{
    asm volatile("mma.sync.aligned.m16n8k16.row.col.f32.bf16.bf16.f32 "
                 "{%0,%1,%2,%3},{%4,%5,%6,%7},{%8,%9},{%0,%1,%2,%3};"
                 : "+f"(c[0]), "+f"(c[1]), "+f"(c[2]), "+f"(c[3])
                 : "r"(a[0]), "r"(a[1]), "r"(a[2]), "r"(a[3]),
                   "r"(b[0]), "r"(b[1]));
}

// smem elem counts (bf16): s_in [2][4][66][24] = 12672 ; s_w [2][9][64][24] = 27648
#define SIN_ELEMS 12672
#define SMEM_BYTES ((12672 + 27648) * 2)

__global__ __launch_bounds__(256, 2)
void convlstm_mma(float* __restrict__ hid_out, float* __restrict__ cell_io,
                  int t, int last)
{
    extern __shared__ __nv_bfloat16 smem[];
    __nv_bfloat16* s_in = smem;               // [sp][sy 4][sx 66][ic 24-pad]
    __nv_bfloat16* s_w  = smem + SIN_ELEMS;   // [sp][tap 9][ocl 64][ic 24-pad]

    const int tid  = threadIdx.x;
    const int w    = tid >> 5;
    const int lane = tid & 31;
    const int y0   = blockIdx.x * 2;      // 2 output rows per block
    const int hcg  = blockIdx.y;          // hidden-ch group (16 each)
    const int b    = blockIdx.z;

    const int par_in  = t & 1;
    const int par_out = (t + 1) & 1;

    const unsigned sIn = (unsigned)__cvta_generic_to_shared(s_in);
    const unsigned sW  = (unsigned)__cvta_generic_to_shared(s_w);

    // lane-invariant ldmatrix offsets
    const int t4 = lane >> 3, r8 = lane & 7;
    const int prA = ((t4 & 1) << 3) + r8;       // row within m16
    const int k8A = t4 >> 1;                    // k-half
    const int p0  = w * 16 + prA;
    const int pyA = p0 >> 6;                    // 0/1 (local y)
    const int pxA = p0 & 63;
    const unsigned laneA = (unsigned)((pyA * 66 + pxA) * 24 + 8 * k8A) * 2u;
    const int hi8 = (t4 >= 2) ? 8 : 0;
    const unsigned laneB = (unsigned)(((hi8 + r8) * 24) + 8 * (t4 & 1)) * 2u;

    float acc[8][4];
#pragma unroll
    for (int i = 0; i < 8; i++)
#pragma unroll
        for (int j = 0; j < 4; j++) acc[i][j] = 0.f;

    const int nkb = (t == 0) ? 4 : 8;    // 16-ch blocks: 4 x-src (+4 h-src)

    for (int kb = 0; kb < nkb; kb++) {
        __syncthreads();
        // stage input tile (2 splits, 4 y-rows, 66 x with halo, 16 ic)
        for (int c = tid; c < 1056; c += 256) {
            int sp   = c / 528;
            int idx  = c - sp * 528;
            int pix  = idx >> 1, half = idx & 1;
            int sy   = pix / 66, sx = pix - sy * 66;
            int gy   = y0 - 1 + sy, gx = sx - 1;
            uint4 v  = make_uint4(0u, 0u, 0u, 0u);
            if ((unsigned)gy < 64u && (unsigned)gx < 64u) {
                const __nv_bfloat16* src = (kb < 4)
                    ? &g_xs[sp][b][t][gy][gx][kb * 16 + half * 8]
                    : &g_hs[par_in][sp][b][gy][gx][(kb - 4) * 16 + half * 8];
                v = *(const uint4*)src;
            }
            *(uint4*)&s_in[((sp * 4 + sy) * 66 + sx) * 24 + half * 8] = v;
        }
        // stage weights for this ic-block, all 9 taps, both splits
        for (int c = tid; c < 2304; c += 256) {
            int sp   = c / 1152;
            int idx  = c - sp * 1152;
            int tap  = idx >> 7;
            int r    = idx & 127;
            int ocl  = r >> 1, half = r & 1;
            int oc   = (ocl >> 4) * 64 + hcg * 16 + (ocl & 15); // gate*64 + hc
            uint4 v  = *(const uint4*)&g_wb[sp][tap][oc][kb * 16 + half * 8];
            *(uint4*)&s_w[((sp * 9 + tap) * 64 + ocl) * 24 + half * 8] = v;
        }
        __syncthreads();

#pragma unroll 1
        for (int tap = 0; tap < 9; tap++) {
            const int dyp = tap / 3, dxp = tap - dyp * 3;
            const unsigned aoff = (unsigned)((dyp * 66 + dxp) * 24) * 2u;

            unsigned a[2][4];
            ldsm4(a[0][0], a[0][1], a[0][2], a[0][3], sIn + aoff + laneA);
            ldsm4(a[1][0], a[1][1], a[1][2], a[1][3],
                  sIn + (unsigned)(4 * 66 * 24) * 2u + aoff + laneA);

            unsigned bf[2][8][2];
#pragma unroll
            for (int sp = 0; sp < 2; sp++) {
                unsigned base = sW + (unsigned)((sp * 9 + tap) * 64 * 24) * 2u + laneB;
#pragma unroll
                for (int j = 0; j < 4; j++) {
                    ldsm4(bf[sp][2 * j][0], bf[sp][2 * j][1],
                          bf[sp][2 * j + 1][0], bf[sp][2 * j + 1][1],
                          base + (unsigned)(16 * j * 24) * 2u);
                }
            }
#pragma unroll
            for (int nf = 0; nf < 8; nf++) {
                mma_bf16(acc[nf], a[0], bf[0][nf]);   // hi*hi
                mma_bf16(acc[nf], a[0], bf[1][nf]);   // hi*w_lo
                mma_bf16(acc[nf], a[1], bf[0][nf]);   // lo*w_hi
            }
        }
    }

    // ---- fused LSTM epilogue ----
    // d-frag: reg0,1 = (row=lane/4, col=c0,c0+1); reg2,3 = (row+8, same cols)
    const int c0    = (lane & 3) * 2;
    const int rbase = lane >> 2;
#pragma unroll
    for (int rr = 0; rr < 2; rr++) {
        const int pe = w * 16 + rbase + 8 * rr;
        const int y  = y0 + (pe >> 6);
        const int x  = pe & 63;
#pragma unroll
        for (int q = 0; q < 4; q++) {
            const int hcl  = c0 + (q & 1) + ((q >> 1) << 3);  // c0,c0+1,c0+8,c0+9
            const int off  = (hcl >= 8) ? 1 : 0;
            const int cidx = (hcl & 7) - c0 + rr * 2;
            float vi = acc[0 + off][cidx];
            float vf = acc[2 + off][cidx];
            float vo = acc[4 + off][cidx];
            float vg = acc[6 + off][cidx];
            float iv = 1.f / (1.f + __expf(-vi));
            float fv = 1.f / (1.f + __expf(-vf));
            float ov = 1.f / (1.f + __expf(-vo));
            float gv = tanhf(vg);
            const int hc = hcg * 16 + hcl;
            const size_t addr = (((size_t)b * 64 + hc) * 64 + y) * 64 + x;
            float cold = (t == 0) ? 0.f : cell_io[addr];
            float cnew = fv * cold + iv * gv;
            cell_io[addr] = cnew;
            float hval = ov * tanhf(cnew);
            if (last) {
                hid_out[addr] = hval;
            } else {
                __nv_bfloat16 hh = __float2bfloat16(hval);
                g_hs[par_out][0][b][y][x][hc] = hh;
                g_hs[par_out][1][b][y][x][hc] =
                    __float2bfloat16(hval - __bfloat162float(hh));
            }
        }
    }
}

extern "C" void kernel_launch(void* const* d_in, const int* in_sizes, int n_in,
                              void* d_out, int out_size)
{
    const float* x  = (const float*)d_in[0];
    const float* Wk = (const float*)d_in[1];
    float* out  = (float*)d_out;
    float* hid  = out;
    float* cell = out + out_size / 2;

    cudaFuncSetAttribute(convlstm_mma,
                         cudaFuncAttributeMaxDynamicSharedMemorySize, SMEM_BYTES);

    prep_w<<<(256 * 128 * 9 + 255) / 256, 256>>>(Wk);
    prep_x<<<8 * 16 * 64, 256>>>(x);

    dim3 grid(32, 4, 8), blk(256);
    for (int t = 0; t < 16; t++)
        convlstm_mma<<<grid, blk, SMEM_BYTES>>>(hid, cell, t, t == 15 ? 1 : 0);
}